// round 6
// baseline (speedup 1.0000x reference)
#include <cuda_runtime.h>
#include <cuda_bf16.h>
#include <math.h>
#include <stdint.h>

#define HH   2048
#define IMOE 1408
#define NE   8
#define TT   2048
#define ISH  2816

// ---------------- scratch (__device__ globals) ----------------
__device__ int   g_cnt[NE];
__device__ int   g_rows[NE * TT];
__device__ int   g_tok2row[TT * 2];
__device__ float g_wt[TT * 2];

__device__ __nv_bfloat16 g_xh[(size_t)TT * HH],  g_xl[(size_t)TT * HH];
__device__ __nv_bfloat16 g_w2h[(size_t)NE * 2 * IMOE * HH], g_w2l[(size_t)NE * 2 * IMOE * HH];
__device__ __nv_bfloat16 g_dwh[(size_t)NE * HH * IMOE],     g_dwl[(size_t)NE * HH * IMOE];
__device__ __nv_bfloat16 g_sw2h[(size_t)2 * ISH * HH],      g_sw2l[(size_t)2 * ISH * HH];
__device__ __nv_bfloat16 g_sdwh[(size_t)HH * ISH],          g_sdwl[(size_t)HH * ISH];
__device__ __nv_bfloat16 g_ah[(size_t)NE * TT * IMOE],      g_al[(size_t)NE * TT * IMOE];
__device__ __nv_bfloat16 g_ash[(size_t)TT * ISH],           g_asl[(size_t)TT * ISH];
__device__ float g_y [(size_t)NE * TT * HH];
__device__ float g_ys[(size_t)TT * HH];

// ---------------- helpers ----------------
__device__ __forceinline__ uint32_t smem_u32(const void* p) {
    uint32_t a;
    asm("{ .reg .u64 t; cvta.to.shared.u64 t, %1; cvt.u32.u64 %0, t; }"
        : "=r"(a) : "l"(p));
    return a;
}
__device__ __forceinline__ void ldsm4(uint32_t* r, uint32_t addr) {
    asm volatile("ldmatrix.sync.aligned.m8n8.x4.shared.b16 {%0,%1,%2,%3}, [%4];"
                 : "=r"(r[0]), "=r"(r[1]), "=r"(r[2]), "=r"(r[3]) : "r"(addr));
}
__device__ __forceinline__ void mma16816(float* d, const uint32_t* a,
                                         uint32_t b0, uint32_t b1) {
    asm volatile("mma.sync.aligned.m16n8k16.row.col.f32.bf16.bf16.f32 "
                 "{%0,%1,%2,%3}, {%4,%5,%6,%7}, {%8,%9}, {%0,%1,%2,%3};"
                 : "+f"(d[0]), "+f"(d[1]), "+f"(d[2]), "+f"(d[3])
                 : "r"(a[0]), "r"(a[1]), "r"(a[2]), "r"(a[3]), "r"(b0), "r"(b1));
}
__device__ __forceinline__ void cpa16(uint32_t dst, const void* src, uint32_t sz) {
    asm volatile("cp.async.cg.shared.global [%0], [%1], 16, %2;"
                 :: "r"(dst), "l"(src), "r"(sz) : "memory");
}
#define CP_COMMIT() asm volatile("cp.async.commit_group;" ::: "memory")
#define CP_WAIT(n)  asm volatile("cp.async.wait_group %0;" :: "n"(n) : "memory")

__device__ __forceinline__ void splitf(float v, __nv_bfloat16& h, __nv_bfloat16& l) {
    h = __float2bfloat16_rn(v);
    l = __float2bfloat16_rn(v - __bfloat162float(h));
}
__device__ __forceinline__ void split4(float4 v, __nv_bfloat162& h0, __nv_bfloat162& h1,
                                       __nv_bfloat162& l0, __nv_bfloat162& l1) {
    __nv_bfloat16 a, b, c, d, e, f, g, h;
    splitf(v.x, a, e); splitf(v.y, b, f); splitf(v.z, c, g); splitf(v.w, d, h);
    h0 = __nv_bfloat162(a, b); h1 = __nv_bfloat162(c, d);
    l0 = __nv_bfloat162(e, f); l1 = __nv_bfloat162(g, h);
}

// ---------------- conversion kernels ----------------
__global__ void split_plain(const float4* __restrict__ src,
                            __nv_bfloat162* __restrict__ dhi,
                            __nv_bfloat162* __restrict__ dlo, size_t n4) {
    size_t stride = (size_t)gridDim.x * blockDim.x;
    for (size_t i = (size_t)blockIdx.x * blockDim.x + threadIdx.x; i < n4; i += stride) {
        __nv_bfloat162 h0, h1, l0, l1;
        split4(src[i], h0, h1, l0, l1);
        dhi[2 * i] = h0; dhi[2 * i + 1] = h1;
        dlo[2 * i] = l0; dlo[2 * i + 1] = l1;
    }
}

// interleave gate/up rows: dst row n -> (n&1 ? up : gate)[n>>1]
template <int NI, int K>
__global__ void interleave_w(const float4* __restrict__ gsrc,
                             const float4* __restrict__ usrc,
                             __nv_bfloat162* __restrict__ dhi,
                             __nv_bfloat162* __restrict__ dlo, int E) {
    const int K4 = K / 4;
    size_t total = (size_t)E * 2 * NI * K4;
    size_t stride = (size_t)gridDim.x * blockDim.x;
    for (size_t i = (size_t)blockIdx.x * blockDim.x + threadIdx.x; i < total; i += stride) {
        int    k4  = (int)(i % K4);
        size_t row = i / K4;
        int    n   = (int)(row % (2 * NI));
        int    e   = (int)(row / (2 * NI));
        const float4* s = (n & 1) ? usrc : gsrc;
        float4 v = s[((size_t)e * NI + (n >> 1)) * K4 + k4];
        __nv_bfloat162 h0, h1, l0, l1;
        split4(v, h0, h1, l0, l1);
        size_t o = i * 2;
        dhi[o] = h0; dhi[o + 1] = h1;
        dlo[o] = l0; dlo[o + 1] = l1;
    }
}

// ---------------- misc kernels ----------------
__global__ void zero_cnt_kernel() {
    if (threadIdx.x < NE) g_cnt[threadIdx.x] = 0;
}

__global__ void router_kernel(const float* __restrict__ x,
                              const float* __restrict__ rw,
                              const float* __restrict__ bias) {
    int t    = (blockIdx.x * blockDim.x + threadIdx.x) >> 5;
    int lane = threadIdx.x & 31;
    if (t >= TT) return;
    const float* xt = x + (size_t)t * HH;

    float logits[NE];
#pragma unroll
    for (int e = 0; e < NE; e++) {
        const float* w = rw + e * HH;
        float s = 0.f;
        for (int h = lane; h < HH; h += 32) s = fmaf(xt[h], w[h], s);
#pragma unroll
        for (int o = 16; o; o >>= 1) s += __shfl_xor_sync(0xffffffffu, s, o);
        logits[e] = s;
    }
    if (lane != 0) return;

    float scores[NE], sfc[NE];
#pragma unroll
    for (int e = 0; e < NE; e++) {
        scores[e] = 1.f / (1.f + expf(-logits[e]));
        sfc[e]    = scores[e] + bias[e];
    }
    float gs[4];
#pragma unroll
    for (int g = 0; g < 4; g++) gs[g] = sfc[2 * g] + sfc[2 * g + 1];
    int g0 = 0;
#pragma unroll
    for (int g = 1; g < 4; g++) if (gs[g] > gs[g0]) g0 = g;
    int g1 = -1;
#pragma unroll
    for (int g = 0; g < 4; g++) {
        if (g == g0) continue;
        if (g1 < 0 || gs[g] > gs[g1]) g1 = g;
    }
    int i0 = -1; float v0 = -1.f;
#pragma unroll
    for (int e = 0; e < NE; e++) {
        int g = e >> 1;
        float v = (g == g0 || g == g1) ? sfc[e] : 0.0f;
        if (v > v0) { v0 = v; i0 = e; }
    }
    int i1 = -1; float v1 = -1.f;
#pragma unroll
    for (int e = 0; e < NE; e++) {
        if (e == i0) continue;
        int g = e >> 1;
        float v = (g == g0 || g == g1) ? sfc[e] : 0.0f;
        if (v > v1) { v1 = v; i1 = e; }
    }
    float w0 = scores[i0], w1 = scores[i1];
    float inv = 2.5f / (w0 + w1 + 1e-20f);
    w0 *= inv; w1 *= inv;

    int p0 = atomicAdd(&g_cnt[i0], 1);
    g_rows[i0 * TT + p0] = t;
    g_tok2row[t * 2 + 0] = i0 * TT + p0;
    g_wt[t * 2 + 0]      = w0;
    int p1 = atomicAdd(&g_cnt[i1], 1);
    g_rows[i1 * TT + p1] = t;
    g_tok2row[t * 2 + 1] = i1 * TT + p1;
    g_wt[t * 2 + 1]      = w1;
}

// ---------------- split-bf16 HMMA GEMM, pre-split operands + cp.async ----------------
// 128x128 CTA tile, BK=32, 8 warps (4m x 2n), double-buffered cp.async.
// Operands already split into hi/lo bf16 planes in gmem.
#define ROWB   80
#define PLANEB (128 * ROWB)       // 10240
#define STAGEB (4 * PLANEB)       // 40960
#define SMEM_SZ (2 * STAGEB)      // 81920

template <int N, int K, bool ROUTED, bool GATHER, bool GATEUP>
__global__ __launch_bounds__(256, 2)
void hmma2(const __nv_bfloat16* __restrict__ Ahi, const __nv_bfloat16* __restrict__ Alo,
           const __nv_bfloat16* __restrict__ Bhi, const __nv_bfloat16* __restrict__ Blo,
           float* __restrict__ D,
           __nv_bfloat16* __restrict__ Phi, __nv_bfloat16* __restrict__ Plo) {
    extern __shared__ __align__(128) char smem[];
    const int e  = blockIdx.z;
    const int M  = ROUTED ? g_cnt[e] : TT;
    const int m0 = blockIdx.y * 128;
    if (m0 >= M) return;
    const int n0   = blockIdx.x * 128;
    const int tid  = threadIdx.x;
    const int lane = tid & 31;
    const int wid  = tid >> 5;
    const int wm   = wid & 3;
    const int wn   = wid >> 2;
    const uint32_t sb0 = smem_u32(smem);

    // loader mapping: 2 threads per row, each thread 2x16B per plane
    const int lr = tid >> 1;
    const int hh = tid & 1;
    const __nv_bfloat16 *pAhi, *pAlo;
    uint32_t asz = 0;
    {
        int row = m0 + lr;
        size_t gr = 0;
        if (row < M) {
            gr  = GATHER ? (size_t)g_rows[e * TT + row]
                         : (ROUTED ? (size_t)e * TT + row : (size_t)row);
            asz = 16;
        }
        pAhi = Ahi + gr * (size_t)K + hh * 16;
        pAlo = Alo + gr * (size_t)K + hh * 16;
    }
    const size_t boff = (ROUTED ? (size_t)e * N * K : 0) + (size_t)(n0 + lr) * K + hh * 16;
    const __nv_bfloat16* pBhi = Bhi + boff;
    const __nv_bfloat16* pBlo = Blo + boff;
    const uint32_t dsto = (uint32_t)lr * ROWB + (uint32_t)hh * 32;

    auto issue = [&](int c, int s) {
        uint32_t d = sb0 + (uint32_t)s * STAGEB + dsto;
        const __nv_bfloat16* a0 = pAhi + c * 32;
        const __nv_bfloat16* a1 = pAlo + c * 32;
        const __nv_bfloat16* b0 = pBhi + c * 32;
        const __nv_bfloat16* b1 = pBlo + c * 32;
        cpa16(d,                  a0,     asz);
        cpa16(d + 16,             a0 + 8, asz);
        cpa16(d + PLANEB,         a1,     asz);
        cpa16(d + PLANEB + 16,    a1 + 8, asz);
        cpa16(d + 2 * PLANEB,      b0,     16);
        cpa16(d + 2 * PLANEB + 16, b0 + 8, 16);
        cpa16(d + 3 * PLANEB,      b1,     16);
        cpa16(d + 3 * PLANEB + 16, b1 + 8, 16);
        CP_COMMIT();
    };

    float acc[2][8][4];
#pragma unroll
    for (int f = 0; f < 2; f++)
#pragma unroll
        for (int j = 0; j < 8; j++)
#pragma unroll
            for (int q = 0; q < 4; q++) acc[f][j][q] = 0.f;

    const int NCH = K / 32;
    issue(0, 0);

    for (int c = 0; c < NCH; c++) {
        const int s = c & 1;
        if (c + 1 < NCH) {
            issue(c + 1, s ^ 1);
            CP_WAIT(1);
        } else {
            CP_WAIT(0);
        }
        __syncthreads();

        const uint32_t stg = sb0 + (uint32_t)s * STAGEB;
#pragma unroll
        for (int ks = 0; ks < 2; ks++) {
            const uint32_t cb = (uint32_t)(ks * 16 + (lane >> 4) * 8) * 2;
            uint32_t aH[2][4], aL[2][4];
#pragma unroll
            for (int f = 0; f < 2; f++) {
                uint32_t ra = (uint32_t)(wm * 32 + f * 16 + (lane & 15)) * ROWB + cb;
                ldsm4(aH[f], stg + ra);
                ldsm4(aL[f], stg + PLANEB + ra);
            }
#pragma unroll
            for (int nb = 0; nb < 4; nb++) {
                uint32_t rb = (uint32_t)(wn * 64 + nb * 16 + (lane & 15)) * ROWB + cb;
                uint32_t h4[4], l4[4];
                ldsm4(h4, stg + 2 * PLANEB + rb);
                ldsm4(l4, stg + 3 * PLANEB + rb);
#pragma unroll
                for (int f = 0; f < 2; f++) {
                    mma16816(acc[f][2 * nb],     aH[f], h4[0], h4[2]);
                    mma16816(acc[f][2 * nb],     aH[f], l4[0], l4[2]);
                    mma16816(acc[f][2 * nb],     aL[f], h4[0], h4[2]);
                    mma16816(acc[f][2 * nb + 1], aH[f], h4[1], h4[3]);
                    mma16816(acc[f][2 * nb + 1], aH[f], l4[1], l4[3]);
                    mma16816(acc[f][2 * nb + 1], aL[f], h4[1], h4[3]);
                }
            }
        }
        __syncthreads();
    }

    // ---- epilogue ----
    const size_t rowbase = ROUTED ? (size_t)e * TT : 0;
#pragma unroll
    for (int f = 0; f < 2; f++) {
#pragma unroll
        for (int half = 0; half < 2; half++) {
            int rloc = m0 + wm * 32 + f * 16 + (lane >> 2) + half * 8;
            if (rloc >= M) continue;
            size_t rg = rowbase + rloc;
#pragma unroll
            for (int j = 0; j < 8; j++) {
                float vx = acc[f][j][half * 2 + 0];
                float vy = acc[f][j][half * 2 + 1];
                int cg = n0 + wn * 64 + j * 8 + (lane & 3) * 2;
                if (GATEUP) {
                    // vx = gate (even col), vy = up (odd col)
                    float a = vx / (1.f + expf(-vx)) * vy;
                    __nv_bfloat16 h, l;
                    splitf(a, h, l);
                    size_t o = rg * (size_t)(N / 2) + (cg >> 1);
                    Phi[o] = h; Plo[o] = l;
                } else {
                    *(float2*)(D + rg * (size_t)N + cg) = make_float2(vx, vy);
                }
            }
        }
    }
}

// ---------------- combine ----------------
__global__ void combine_kernel(float4* __restrict__ out) {
    int idx = blockIdx.x * blockDim.x + threadIdx.x;
    if (idx >= TT * HH / 4) return;
    int t  = idx >> 9;
    int h4 = idx & 511;
    float w0 = g_wt[2 * t], w1 = g_wt[2 * t + 1];
    float4 a = *((const float4*)(g_y + (size_t)g_tok2row[2 * t]     * HH) + h4);
    float4 b = *((const float4*)(g_y + (size_t)g_tok2row[2 * t + 1] * HH) + h4);
    float4 c = *((const float4*)g_ys + idx);
    float4 o;
    o.x = fmaf(w0, a.x, fmaf(w1, b.x, c.x));
    o.y = fmaf(w0, a.y, fmaf(w1, b.y, c.y));
    o.z = fmaf(w0, a.z, fmaf(w1, b.z, c.z));
    o.w = fmaf(w0, a.w, fmaf(w1, b.w, c.w));
    out[idx] = o;
}

// ---------------- launch ----------------
extern "C" void kernel_launch(void* const* d_in, const int* in_sizes, int n_in,
                              void* d_out, int out_size) {
    const float* x    = (const float*)d_in[0];
    const float* rw   = (const float*)d_in[1];
    const float* bias = (const float*)d_in[2];
    const float* gw   = (const float*)d_in[3];
    const float* uw   = (const float*)d_in[4];
    const float* dw   = (const float*)d_in[5];
    const float* sgw  = (const float*)d_in[6];
    const float* suw  = (const float*)d_in[7];
    const float* sdw  = (const float*)d_in[8];
    float* out = (float*)d_out;

    __nv_bfloat16 *xh, *xl, *w2h, *w2l, *dwh, *dwl, *sw2h, *sw2l, *sdwh, *sdwl,
                  *ah, *al, *ash, *asl;
    float *py, *pys;
    cudaGetSymbolAddress((void**)&xh,   g_xh);   cudaGetSymbolAddress((void**)&xl,   g_xl);
    cudaGetSymbolAddress((void**)&w2h,  g_w2h);  cudaGetSymbolAddress((void**)&w2l,  g_w2l);
    cudaGetSymbolAddress((void**)&dwh,  g_dwh);  cudaGetSymbolAddress((void**)&dwl,  g_dwl);
    cudaGetSymbolAddress((void**)&sw2h, g_sw2h); cudaGetSymbolAddress((void**)&sw2l, g_sw2l);
    cudaGetSymbolAddress((void**)&sdwh, g_sdwh); cudaGetSymbolAddress((void**)&sdwl, g_sdwl);
    cudaGetSymbolAddress((void**)&ah,   g_ah);   cudaGetSymbolAddress((void**)&al,   g_al);
    cudaGetSymbolAddress((void**)&ash,  g_ash);  cudaGetSymbolAddress((void**)&asl,  g_asl);
    cudaGetSymbolAddress((void**)&py,   g_y);    cudaGetSymbolAddress((void**)&pys,  g_ys);

    cudaFuncSetAttribute(hmma2<2 * IMOE, HH, true,  true,  true >, cudaFuncAttributeMaxDynamicSharedMemorySize, SMEM_SZ);
    cudaFuncSetAttribute(hmma2<HH, IMOE, true,  false, false>, cudaFuncAttributeMaxDynamicSharedMemorySize, SMEM_SZ);
    cudaFuncSetAttribute(hmma2<2 * ISH,  HH, false, false, true >, cudaFuncAttributeMaxDynamicSharedMemorySize, SMEM_SZ);
    cudaFuncSetAttribute(hmma2<HH,  ISH, false, false, false>, cudaFuncAttributeMaxDynamicSharedMemorySize, SMEM_SZ);

    zero_cnt_kernel<<<1, 32>>>();
    router_kernel<<<TT / 8, 256>>>(x, rw, bias);

    // pre-split conversions
    {
        size_t n4 = (size_t)TT * HH / 4;
        split_plain<<<(unsigned)((n4 + 255) / 256), 256>>>((const float4*)x,
            (__nv_bfloat162*)xh, (__nv_bfloat162*)xl, n4);
    }
    {
        size_t total = (size_t)NE * 2 * IMOE * (HH / 4);
        interleave_w<IMOE, HH><<<(unsigned)((total + 255) / 256), 256>>>(
            (const float4*)gw, (const float4*)uw,
            (__nv_bfloat162*)w2h, (__nv_bfloat162*)w2l, NE);
    }
    {
        size_t n4 = (size_t)NE * HH * IMOE / 4;
        split_plain<<<(unsigned)((n4 + 255) / 256), 256>>>((const float4*)dw,
            (__nv_bfloat162*)dwh, (__nv_bfloat162*)dwl, n4);
    }
    {
        size_t total = (size_t)2 * ISH * (HH / 4);
        interleave_w<ISH, HH><<<(unsigned)((total + 255) / 256), 256>>>(
            (const float4*)sgw, (const float4*)suw,
            (__nv_bfloat162*)sw2h, (__nv_bfloat162*)sw2l, 1);
    }
    {
        size_t n4 = (size_t)HH * ISH / 4;
        split_plain<<<(unsigned)((n4 + 255) / 256), 256>>>((const float4*)sdw,
            (__nv_bfloat162*)sdwh, (__nv_bfloat162*)sdwl, n4);
    }

    // routed: fused gate+up (interleaved) -> act planes; then down
    hmma2<2 * IMOE, HH, true, true, true><<<dim3(2 * IMOE / 128, TT / 128, NE), 256, SMEM_SZ>>>(
        xh, xl, w2h, w2l, nullptr, ah, al);
    hmma2<HH, IMOE, true, false, false><<<dim3(HH / 128, TT / 128, NE), 256, SMEM_SZ>>>(
        ah, al, dwh, dwl, py, nullptr, nullptr);

    // shared expert
    hmma2<2 * ISH, HH, false, false, true><<<dim3(2 * ISH / 128, TT / 128, 1), 256, SMEM_SZ>>>(
        xh, xl, sw2h, sw2l, nullptr, ash, asl);
    hmma2<HH, ISH, false, false, false><<<dim3(HH / 128, TT / 128, 1), 256, SMEM_SZ>>>(
        ash, asl, sdwh, sdwl, pys, nullptr, nullptr);

    combine_kernel<<<(TT * HH / 4 + 255) / 256, 256>>>((float4*)out);
}

// round 7
// speedup vs baseline: 1.3254x; 1.3254x over previous
#include <cuda_runtime.h>
#include <cuda_bf16.h>
#include <math.h>
#include <stdint.h>

#define HH   2048
#define IMOE 1408
#define NE   8
#define TT   2048
#define ISH  2816

// ---------------- scratch (__device__ globals) ----------------
__device__ int   g_cnt[NE];
__device__ int   g_rows[NE * TT];
__device__ int   g_tok2row[TT * 2];
__device__ float g_wt[TT * 2];

__device__ __nv_bfloat16 g_xh[(size_t)TT * HH],  g_xl[(size_t)TT * HH];
__device__ __nv_bfloat16 g_w2h[(size_t)NE * 2 * IMOE * HH], g_w2l[(size_t)NE * 2 * IMOE * HH];
__device__ __nv_bfloat16 g_dwh[(size_t)NE * HH * IMOE],     g_dwl[(size_t)NE * HH * IMOE];
__device__ __nv_bfloat16 g_sw2h[(size_t)2 * ISH * HH],      g_sw2l[(size_t)2 * ISH * HH];
__device__ __nv_bfloat16 g_sdwh[(size_t)HH * ISH],          g_sdwl[(size_t)HH * ISH];
__device__ __nv_bfloat16 g_ah[(size_t)NE * TT * IMOE],      g_al[(size_t)NE * TT * IMOE];
__device__ __nv_bfloat16 g_ash[(size_t)TT * ISH],           g_asl[(size_t)TT * ISH];
__device__ float g_y [(size_t)NE * TT * HH];
__device__ float g_ys[(size_t)TT * HH];

// ---------------- helpers ----------------
__device__ __forceinline__ uint32_t smem_u32(const void* p) {
    uint32_t a;
    asm("{ .reg .u64 t; cvta.to.shared.u64 t, %1; cvt.u32.u64 %0, t; }"
        : "=r"(a) : "l"(p));
    return a;
}
__device__ __forceinline__ void ldsm4(uint32_t* r, uint32_t addr) {
    asm volatile("ldmatrix.sync.aligned.m8n8.x4.shared.b16 {%0,%1,%2,%3}, [%4];"
                 : "=r"(r[0]), "=r"(r[1]), "=r"(r[2]), "=r"(r[3]) : "r"(addr));
}
__device__ __forceinline__ void mma16816(float* d, const uint32_t* a,
                                         uint32_t b0, uint32_t b1) {
    asm volatile("mma.sync.aligned.m16n8k16.row.col.f32.bf16.bf16.f32 "
                 "{%0,%1,%2,%3}, {%4,%5,%6,%7}, {%8,%9}, {%0,%1,%2,%3};"
                 : "+f"(d[0]), "+f"(d[1]), "+f"(d[2]), "+f"(d[3])
                 : "r"(a[0]), "r"(a[1]), "r"(a[2]), "r"(a[3]), "r"(b0), "r"(b1));
}
__device__ __forceinline__ void cpa16(uint32_t dst, const void* src, uint32_t sz) {
    asm volatile("cp.async.cg.shared.global [%0], [%1], 16, %2;"
                 :: "r"(dst), "l"(src), "r"(sz) : "memory");
}
#define CP_COMMIT() asm volatile("cp.async.commit_group;" ::: "memory")
#define CP_WAIT(n)  asm volatile("cp.async.wait_group %0;" :: "n"(n) : "memory")

__device__ __forceinline__ void splitf(float v, __nv_bfloat16& h, __nv_bfloat16& l) {
    h = __float2bfloat16_rn(v);
    l = __float2bfloat16_rn(v - __bfloat162float(h));
}
__device__ __forceinline__ void split4(float4 v, __nv_bfloat162& h0, __nv_bfloat162& h1,
                                       __nv_bfloat162& l0, __nv_bfloat162& l1) {
    __nv_bfloat16 a, b, c, d, e, f, g, h;
    splitf(v.x, a, e); splitf(v.y, b, f); splitf(v.z, c, g); splitf(v.w, d, h);
    h0 = __nv_bfloat162(a, b); h1 = __nv_bfloat162(c, d);
    l0 = __nv_bfloat162(e, f); l1 = __nv_bfloat162(g, h);
}

// ---------------- conversion kernels ----------------
__global__ void split_plain(const float4* __restrict__ src,
                            __nv_bfloat162* __restrict__ dhi,
                            __nv_bfloat162* __restrict__ dlo, size_t n4) {
    size_t stride = (size_t)gridDim.x * blockDim.x;
    for (size_t i = (size_t)blockIdx.x * blockDim.x + threadIdx.x; i < n4; i += stride) {
        __nv_bfloat162 h0, h1, l0, l1;
        split4(src[i], h0, h1, l0, l1);
        dhi[2 * i] = h0; dhi[2 * i + 1] = h1;
        dlo[2 * i] = l0; dlo[2 * i + 1] = l1;
    }
}

// interleave gate/up rows: dst row n -> (n&1 ? up : gate)[n>>1]
template <int NI, int K>
__global__ void interleave_w(const float4* __restrict__ gsrc,
                             const float4* __restrict__ usrc,
                             __nv_bfloat162* __restrict__ dhi,
                             __nv_bfloat162* __restrict__ dlo, int E) {
    const int K4 = K / 4;
    size_t total = (size_t)E * 2 * NI * K4;
    size_t stride = (size_t)gridDim.x * blockDim.x;
    for (size_t i = (size_t)blockIdx.x * blockDim.x + threadIdx.x; i < total; i += stride) {
        int    k4  = (int)(i % K4);
        size_t row = i / K4;
        int    n   = (int)(row % (2 * NI));
        int    e   = (int)(row / (2 * NI));
        const float4* s = (n & 1) ? usrc : gsrc;
        float4 v = s[((size_t)e * NI + (n >> 1)) * K4 + k4];
        __nv_bfloat162 h0, h1, l0, l1;
        split4(v, h0, h1, l0, l1);
        size_t o = i * 2;
        dhi[o] = h0; dhi[o + 1] = h1;
        dlo[o] = l0; dlo[o + 1] = l1;
    }
}

// ---------------- misc kernels ----------------
__global__ void zero_cnt_kernel() {
    if (threadIdx.x < NE) g_cnt[threadIdx.x] = 0;
}

__global__ void router_kernel(const float* __restrict__ x,
                              const float* __restrict__ rw,
                              const float* __restrict__ bias) {
    int t    = (blockIdx.x * blockDim.x + threadIdx.x) >> 5;
    int lane = threadIdx.x & 31;
    if (t >= TT) return;
    const float* xt = x + (size_t)t * HH;

    float logits[NE];
#pragma unroll
    for (int e = 0; e < NE; e++) {
        const float* w = rw + e * HH;
        float s = 0.f;
        for (int h = lane; h < HH; h += 32) s = fmaf(xt[h], w[h], s);
#pragma unroll
        for (int o = 16; o; o >>= 1) s += __shfl_xor_sync(0xffffffffu, s, o);
        logits[e] = s;
    }
    if (lane != 0) return;

    float scores[NE], sfc[NE];
#pragma unroll
    for (int e = 0; e < NE; e++) {
        scores[e] = 1.f / (1.f + expf(-logits[e]));
        sfc[e]    = scores[e] + bias[e];
    }
    float gs[4];
#pragma unroll
    for (int g = 0; g < 4; g++) gs[g] = sfc[2 * g] + sfc[2 * g + 1];
    int g0 = 0;
#pragma unroll
    for (int g = 1; g < 4; g++) if (gs[g] > gs[g0]) g0 = g;
    int g1 = -1;
#pragma unroll
    for (int g = 0; g < 4; g++) {
        if (g == g0) continue;
        if (g1 < 0 || gs[g] > gs[g1]) g1 = g;
    }
    int i0 = -1; float v0 = -1.f;
#pragma unroll
    for (int e = 0; e < NE; e++) {
        int g = e >> 1;
        float v = (g == g0 || g == g1) ? sfc[e] : 0.0f;
        if (v > v0) { v0 = v; i0 = e; }
    }
    int i1 = -1; float v1 = -1.f;
#pragma unroll
    for (int e = 0; e < NE; e++) {
        if (e == i0) continue;
        int g = e >> 1;
        float v = (g == g0 || g == g1) ? sfc[e] : 0.0f;
        if (v > v1) { v1 = v; i1 = e; }
    }
    float w0 = scores[i0], w1 = scores[i1];
    float inv = 2.5f / (w0 + w1 + 1e-20f);
    w0 *= inv; w1 *= inv;

    int p0 = atomicAdd(&g_cnt[i0], 1);
    g_rows[i0 * TT + p0] = t;
    g_tok2row[t * 2 + 0] = i0 * TT + p0;
    g_wt[t * 2 + 0]      = w0;
    int p1 = atomicAdd(&g_cnt[i1], 1);
    g_rows[i1 * TT + p1] = t;
    g_tok2row[t * 2 + 1] = i1 * TT + p1;
    g_wt[t * 2 + 1]      = w1;
}

// ---------------- split-bf16 HMMA GEMM, pre-split operands + cp.async ----------------
// 128x128 CTA tile, BK=32, 8 warps (4m x 2n), 3-stage cp.async pipeline.
// MMA combos issued as separate sweeps: 16 independent MMAs between accumulator reuse.
#define ROWB   80
#define PLANEB (128 * ROWB)       // 10240
#define STAGEB (4 * PLANEB)       // 40960
#define NSTG   3
#define SMEM_SZ (NSTG * STAGEB)   // 122880

template <int N, int K, bool ROUTED, bool GATHER, bool GATEUP>
__global__ __launch_bounds__(256)
void hmma2(const __nv_bfloat16* __restrict__ Ahi, const __nv_bfloat16* __restrict__ Alo,
           const __nv_bfloat16* __restrict__ Bhi, const __nv_bfloat16* __restrict__ Blo,
           float* __restrict__ D,
           __nv_bfloat16* __restrict__ Phi, __nv_bfloat16* __restrict__ Plo) {
    extern __shared__ __align__(128) char smem[];
    const int e  = blockIdx.z;
    const int M  = ROUTED ? g_cnt[e] : TT;
    const int m0 = blockIdx.y * 128;
    if (m0 >= M) return;
    const int n0   = blockIdx.x * 128;
    const int tid  = threadIdx.x;
    const int lane = tid & 31;
    const int wid  = tid >> 5;
    const int wm   = wid & 3;
    const int wn   = wid >> 2;
    const uint32_t sb0 = smem_u32(smem);

    // loader mapping: 2 threads per row, each thread 2x16B per plane
    const int lr = tid >> 1;
    const int hh = tid & 1;
    const __nv_bfloat16 *pAhi, *pAlo;
    uint32_t asz = 0;
    {
        int row = m0 + lr;
        size_t gr = 0;
        if (row < M) {
            gr  = GATHER ? (size_t)g_rows[e * TT + row]
                         : (ROUTED ? (size_t)e * TT + row : (size_t)row);
            asz = 16;
        }
        pAhi = Ahi + gr * (size_t)K + hh * 16;
        pAlo = Alo + gr * (size_t)K + hh * 16;
    }
    const size_t boff = (ROUTED ? (size_t)e * N * K : 0) + (size_t)(n0 + lr) * K + hh * 16;
    const __nv_bfloat16* pBhi = Bhi + boff;
    const __nv_bfloat16* pBlo = Blo + boff;
    const uint32_t dsto = (uint32_t)lr * ROWB + (uint32_t)hh * 32;

    auto issue = [&](int c, int s) {
        uint32_t d = sb0 + (uint32_t)s * STAGEB + dsto;
        const __nv_bfloat16* a0 = pAhi + c * 32;
        const __nv_bfloat16* a1 = pAlo + c * 32;
        const __nv_bfloat16* b0 = pBhi + c * 32;
        const __nv_bfloat16* b1 = pBlo + c * 32;
        cpa16(d,                  a0,     asz);
        cpa16(d + 16,             a0 + 8, asz);
        cpa16(d + PLANEB,         a1,     asz);
        cpa16(d + PLANEB + 16,    a1 + 8, asz);
        cpa16(d + 2 * PLANEB,      b0,     16);
        cpa16(d + 2 * PLANEB + 16, b0 + 8, 16);
        cpa16(d + 3 * PLANEB,      b1,     16);
        cpa16(d + 3 * PLANEB + 16, b1 + 8, 16);
        CP_COMMIT();
    };

    float acc[2][8][4];
#pragma unroll
    for (int f = 0; f < 2; f++)
#pragma unroll
        for (int j = 0; j < 8; j++)
#pragma unroll
            for (int q = 0; q < 4; q++) acc[f][j][q] = 0.f;

    const int NCH = K / 32;
    issue(0, 0);
    issue(1, 1);

    for (int c = 0; c < NCH; c++) {
        const int s = c % NSTG;
        if (c + 2 < NCH) {
            issue(c + 2, (c + 2) % NSTG);
            CP_WAIT(2);
        } else if (c + 1 < NCH) {
            CP_WAIT(1);
        } else {
            CP_WAIT(0);
        }
        __syncthreads();

        const uint32_t stg = sb0 + (uint32_t)s * STAGEB;
#pragma unroll
        for (int ks = 0; ks < 2; ks++) {
            const uint32_t cb = (uint32_t)(ks * 16 + (lane >> 4) * 8) * 2;
            uint32_t aH[2][4], aL[2][4], bH[8][2], bL[8][2];
#pragma unroll
            for (int f = 0; f < 2; f++) {
                uint32_t ra = (uint32_t)(wm * 32 + f * 16 + (lane & 15)) * ROWB + cb;
                ldsm4(aH[f], stg + ra);
                ldsm4(aL[f], stg + PLANEB + ra);
            }
#pragma unroll
            for (int nb = 0; nb < 4; nb++) {
                uint32_t rb = (uint32_t)(wn * 64 + nb * 16 + (lane & 15)) * ROWB + cb;
                uint32_t h4[4], l4[4];
                ldsm4(h4, stg + 2 * PLANEB + rb);
                ldsm4(l4, stg + 3 * PLANEB + rb);
                bH[2 * nb][0] = h4[0]; bH[2 * nb][1] = h4[2];
                bH[2 * nb + 1][0] = h4[1]; bH[2 * nb + 1][1] = h4[3];
                bL[2 * nb][0] = l4[0]; bL[2 * nb][1] = l4[2];
                bL[2 * nb + 1][0] = l4[1]; bL[2 * nb + 1][1] = l4[3];
            }
            // combo sweeps: same accumulator reused only every 16 MMAs
#pragma unroll
            for (int f = 0; f < 2; f++)
#pragma unroll
                for (int j = 0; j < 8; j++)
                    mma16816(acc[f][j], aH[f], bH[j][0], bH[j][1]);
#pragma unroll
            for (int f = 0; f < 2; f++)
#pragma unroll
                for (int j = 0; j < 8; j++)
                    mma16816(acc[f][j], aH[f], bL[j][0], bL[j][1]);
#pragma unroll
            for (int f = 0; f < 2; f++)
#pragma unroll
                for (int j = 0; j < 8; j++)
                    mma16816(acc[f][j], aL[f], bH[j][0], bH[j][1]);
        }
        __syncthreads();
    }

    // ---- epilogue ----
    const size_t rowbase = ROUTED ? (size_t)e * TT : 0;
#pragma unroll
    for (int f = 0; f < 2; f++) {
#pragma unroll
        for (int half = 0; half < 2; half++) {
            int rloc = m0 + wm * 32 + f * 16 + (lane >> 2) + half * 8;
            if (rloc >= M) continue;
            size_t rg = rowbase + rloc;
#pragma unroll
            for (int j = 0; j < 8; j++) {
                float vx = acc[f][j][half * 2 + 0];
                float vy = acc[f][j][half * 2 + 1];
                int cg = n0 + wn * 64 + j * 8 + (lane & 3) * 2;
                if (GATEUP) {
                    // vx = gate (even col), vy = up (odd col)
                    float a = vx / (1.f + expf(-vx)) * vy;
                    __nv_bfloat16 h, l;
                    splitf(a, h, l);
                    size_t o = rg * (size_t)(N / 2) + (cg >> 1);
                    Phi[o] = h; Plo[o] = l;
                } else {
                    *(float2*)(D + rg * (size_t)N + cg) = make_float2(vx, vy);
                }
            }
        }
    }
}

// ---------------- combine ----------------
__global__ void combine_kernel(float4* __restrict__ out) {
    int idx = blockIdx.x * blockDim.x + threadIdx.x;
    if (idx >= TT * HH / 4) return;
    int t  = idx >> 9;
    int h4 = idx & 511;
    float w0 = g_wt[2 * t], w1 = g_wt[2 * t + 1];
    float4 a = *((const float4*)(g_y + (size_t)g_tok2row[2 * t]     * HH) + h4);
    float4 b = *((const float4*)(g_y + (size_t)g_tok2row[2 * t + 1] * HH) + h4);
    float4 c = *((const float4*)g_ys + idx);
    float4 o;
    o.x = fmaf(w0, a.x, fmaf(w1, b.x, c.x));
    o.y = fmaf(w0, a.y, fmaf(w1, b.y, c.y));
    o.z = fmaf(w0, a.z, fmaf(w1, b.z, c.z));
    o.w = fmaf(w0, a.w, fmaf(w1, b.w, c.w));
    out[idx] = o;
}

// ---------------- launch ----------------
extern "C" void kernel_launch(void* const* d_in, const int* in_sizes, int n_in,
                              void* d_out, int out_size) {
    const float* x    = (const float*)d_in[0];
    const float* rw   = (const float*)d_in[1];
    const float* bias = (const float*)d_in[2];
    const float* gw   = (const float*)d_in[3];
    const float* uw   = (const float*)d_in[4];
    const float* dw   = (const float*)d_in[5];
    const float* sgw  = (const float*)d_in[6];
    const float* suw  = (const float*)d_in[7];
    const float* sdw  = (const float*)d_in[8];
    float* out = (float*)d_out;

    __nv_bfloat16 *xh, *xl, *w2h, *w2l, *dwh, *dwl, *sw2h, *sw2l, *sdwh, *sdwl,
                  *ah, *al, *ash, *asl;
    float *py, *pys;
    cudaGetSymbolAddress((void**)&xh,   g_xh);   cudaGetSymbolAddress((void**)&xl,   g_xl);
    cudaGetSymbolAddress((void**)&w2h,  g_w2h);  cudaGetSymbolAddress((void**)&w2l,  g_w2l);
    cudaGetSymbolAddress((void**)&dwh,  g_dwh);  cudaGetSymbolAddress((void**)&dwl,  g_dwl);
    cudaGetSymbolAddress((void**)&sw2h, g_sw2h); cudaGetSymbolAddress((void**)&sw2l, g_sw2l);
    cudaGetSymbolAddress((void**)&sdwh, g_sdwh); cudaGetSymbolAddress((void**)&sdwl, g_sdwl);
    cudaGetSymbolAddress((void**)&ah,   g_ah);   cudaGetSymbolAddress((void**)&al,   g_al);
    cudaGetSymbolAddress((void**)&ash,  g_ash);  cudaGetSymbolAddress((void**)&asl,  g_asl);
    cudaGetSymbolAddress((void**)&py,   g_y);    cudaGetSymbolAddress((void**)&pys,  g_ys);

    cudaFuncSetAttribute(hmma2<2 * IMOE, HH, true,  true,  true >, cudaFuncAttributeMaxDynamicSharedMemorySize, SMEM_SZ);
    cudaFuncSetAttribute(hmma2<HH, IMOE, true,  false, false>, cudaFuncAttributeMaxDynamicSharedMemorySize, SMEM_SZ);
    cudaFuncSetAttribute(hmma2<2 * ISH,  HH, false, false, true >, cudaFuncAttributeMaxDynamicSharedMemorySize, SMEM_SZ);
    cudaFuncSetAttribute(hmma2<HH,  ISH, false, false, false>, cudaFuncAttributeMaxDynamicSharedMemorySize, SMEM_SZ);

    zero_cnt_kernel<<<1, 32>>>();
    router_kernel<<<TT / 8, 256>>>(x, rw, bias);

    // pre-split conversions
    {
        size_t n4 = (size_t)TT * HH / 4;
        split_plain<<<(unsigned)((n4 + 255) / 256), 256>>>((const float4*)x,
            (__nv_bfloat162*)xh, (__nv_bfloat162*)xl, n4);
    }
    {
        size_t total = (size_t)NE * 2 * IMOE * (HH / 4);
        interleave_w<IMOE, HH><<<(unsigned)((total + 255) / 256), 256>>>(
            (const float4*)gw, (const float4*)uw,
            (__nv_bfloat162*)w2h, (__nv_bfloat162*)w2l, NE);
    }
    {
        size_t n4 = (size_t)NE * HH * IMOE / 4;
        split_plain<<<(unsigned)((n4 + 255) / 256), 256>>>((const float4*)dw,
            (__nv_bfloat162*)dwh, (__nv_bfloat162*)dwl, n4);
    }
    {
        size_t total = (size_t)2 * ISH * (HH / 4);
        interleave_w<ISH, HH><<<(unsigned)((total + 255) / 256), 256>>>(
            (const float4*)sgw, (const float4*)suw,
            (__nv_bfloat162*)sw2h, (__nv_bfloat162*)sw2l, 1);
    }
    {
        size_t n4 = (size_t)HH * ISH / 4;
        split_plain<<<(unsigned)((n4 + 255) / 256), 256>>>((const float4*)sdw,
            (__nv_bfloat162*)sdwh, (__nv_bfloat162*)sdwl, n4);
    }

    // routed: fused gate+up (interleaved) -> act planes; then down
    hmma2<2 * IMOE, HH, true, true, true><<<dim3(2 * IMOE / 128, TT / 128, NE), 256, SMEM_SZ>>>(
        xh, xl, w2h, w2l, nullptr, ah, al);
    hmma2<HH, IMOE, true, false, false><<<dim3(HH / 128, TT / 128, NE), 256, SMEM_SZ>>>(
        ah, al, dwh, dwl, py, nullptr, nullptr);

    // shared expert
    hmma2<2 * ISH, HH, false, false, true><<<dim3(2 * ISH / 128, TT / 128, 1), 256, SMEM_SZ>>>(
        xh, xl, sw2h, sw2l, nullptr, ash, asl);
    hmma2<HH, ISH, false, false, false><<<dim3(HH / 128, TT / 128, 1), 256, SMEM_SZ>>>(
        ash, asl, sdwh, sdwl, pys, nullptr, nullptr);

    combine_kernel<<<(TT * HH / 4 + 255) / 256, 256>>>((float4*)out);
}

// round 8
// speedup vs baseline: 2.0344x; 1.5349x over previous
#include <cuda_runtime.h>
#include <cuda_fp16.h>
#include <math.h>
#include <stdint.h>

#define HH   2048
#define IMOE 1408
#define NE   8
#define TT   2048
#define ISH  2816

// ---------------- scratch (__device__ globals) ----------------
__device__ int   g_cnt[NE];
__device__ int   g_rows[NE * TT];
__device__ int   g_tok2row[TT * 2];
__device__ float g_wt[TT * 2];

__device__ __half g_xh[(size_t)TT * HH],  g_xl[(size_t)TT * HH];
__device__ __half g_w2 [(size_t)NE * 2 * IMOE * HH];
__device__ __half g_dw [(size_t)NE * HH * IMOE];
__device__ __half g_sw2[(size_t)2 * ISH * HH];
__device__ __half g_sdw[(size_t)HH * ISH];
__device__ __half g_ah[(size_t)NE * TT * IMOE], g_al[(size_t)NE * TT * IMOE];
__device__ __half g_ash[(size_t)TT * ISH],      g_asl[(size_t)TT * ISH];
__device__ float g_y [(size_t)NE * TT * HH];
__device__ float g_ys[(size_t)TT * HH];

// ---------------- helpers ----------------
__device__ __forceinline__ uint32_t smem_u32(const void* p) {
    uint32_t a;
    asm("{ .reg .u64 t; cvta.to.shared.u64 t, %1; cvt.u32.u64 %0, t; }"
        : "=r"(a) : "l"(p));
    return a;
}
__device__ __forceinline__ void ldsm4(uint32_t* r, uint32_t addr) {
    asm volatile("ldmatrix.sync.aligned.m8n8.x4.shared.b16 {%0,%1,%2,%3}, [%4];"
                 : "=r"(r[0]), "=r"(r[1]), "=r"(r[2]), "=r"(r[3]) : "r"(addr));
}
__device__ __forceinline__ void mma16816(float* d, const uint32_t* a,
                                         uint32_t b0, uint32_t b1) {
    asm volatile("mma.sync.aligned.m16n8k16.row.col.f32.f16.f16.f32 "
                 "{%0,%1,%2,%3}, {%4,%5,%6,%7}, {%8,%9}, {%0,%1,%2,%3};"
                 : "+f"(d[0]), "+f"(d[1]), "+f"(d[2]), "+f"(d[3])
                 : "r"(a[0]), "r"(a[1]), "r"(a[2]), "r"(a[3]), "r"(b0), "r"(b1));
}
__device__ __forceinline__ void cpa16(uint32_t dst, const void* src, uint32_t sz) {
    asm volatile("cp.async.cg.shared.global [%0], [%1], 16, %2;"
                 :: "r"(dst), "l"(src), "r"(sz) : "memory");
}
#define CP_COMMIT() asm volatile("cp.async.commit_group;" ::: "memory")
#define CP_WAIT(n)  asm volatile("cp.async.wait_group %0;" :: "n"(n) : "memory")

__device__ __forceinline__ void splith(float v, __half& h, __half& l) {
    h = __float2half_rn(v);
    l = __float2half_rn(v - __half2float(h));
}

// ---------------- conversion kernels ----------------
// fp32 -> fp16 hi/lo split (for x)
__global__ void cvt_split16(const float4* __restrict__ src,
                            __half2* __restrict__ dhi,
                            __half2* __restrict__ dlo, size_t n4) {
    size_t stride = (size_t)gridDim.x * blockDim.x;
    for (size_t i = (size_t)blockIdx.x * blockDim.x + threadIdx.x; i < n4; i += stride) {
        float4 v = src[i];
        __half a, b, c, d, e, f, g, h;
        splith(v.x, a, e); splith(v.y, b, f); splith(v.z, c, g); splith(v.w, d, h);
        dhi[2 * i]     = __half2(a, b);
        dhi[2 * i + 1] = __half2(c, d);
        dlo[2 * i]     = __half2(e, f);
        dlo[2 * i + 1] = __half2(g, h);
    }
}

// fp32 -> fp16 single plane (for down weights)
__global__ void cvt_plain16(const float4* __restrict__ src,
                            __half2* __restrict__ dst, size_t n4) {
    size_t stride = (size_t)gridDim.x * blockDim.x;
    for (size_t i = (size_t)blockIdx.x * blockDim.x + threadIdx.x; i < n4; i += stride) {
        float4 v = src[i];
        dst[2 * i]     = __half2(__float2half_rn(v.x), __float2half_rn(v.y));
        dst[2 * i + 1] = __half2(__float2half_rn(v.z), __float2half_rn(v.w));
    }
}

// interleave gate/up rows to single fp16 plane: dst row n -> (n&1 ? up : gate)[n>>1]
template <int NI, int K>
__global__ void interleave_w16(const float4* __restrict__ gsrc,
                               const float4* __restrict__ usrc,
                               __half2* __restrict__ dst, int E) {
    const int K4 = K / 4;
    size_t total = (size_t)E * 2 * NI * K4;
    size_t stride = (size_t)gridDim.x * blockDim.x;
    for (size_t i = (size_t)blockIdx.x * blockDim.x + threadIdx.x; i < total; i += stride) {
        int    k4  = (int)(i % K4);
        size_t row = i / K4;
        int    n   = (int)(row % (2 * NI));
        int    e   = (int)(row / (2 * NI));
        const float4* s = (n & 1) ? usrc : gsrc;
        float4 v = s[((size_t)e * NI + (n >> 1)) * K4 + k4];
        dst[2 * i]     = __half2(__float2half_rn(v.x), __float2half_rn(v.y));
        dst[2 * i + 1] = __half2(__float2half_rn(v.z), __float2half_rn(v.w));
    }
}

// ---------------- misc kernels ----------------
__global__ void zero_cnt_kernel() {
    if (threadIdx.x < NE) g_cnt[threadIdx.x] = 0;
}

__global__ void router_kernel(const float* __restrict__ x,
                              const float* __restrict__ rw,
                              const float* __restrict__ bias) {
    int t    = (blockIdx.x * blockDim.x + threadIdx.x) >> 5;
    int lane = threadIdx.x & 31;
    if (t >= TT) return;
    const float* xt = x + (size_t)t * HH;

    float logits[NE];
#pragma unroll
    for (int e = 0; e < NE; e++) {
        const float* w = rw + e * HH;
        float s = 0.f;
        for (int h = lane; h < HH; h += 32) s = fmaf(xt[h], w[h], s);
#pragma unroll
        for (int o = 16; o; o >>= 1) s += __shfl_xor_sync(0xffffffffu, s, o);
        logits[e] = s;
    }
    if (lane != 0) return;

    float scores[NE], sfc[NE];
#pragma unroll
    for (int e = 0; e < NE; e++) {
        scores[e] = 1.f / (1.f + expf(-logits[e]));
        sfc[e]    = scores[e] + bias[e];
    }
    float gs[4];
#pragma unroll
    for (int g = 0; g < 4; g++) gs[g] = sfc[2 * g] + sfc[2 * g + 1];
    int g0 = 0;
#pragma unroll
    for (int g = 1; g < 4; g++) if (gs[g] > gs[g0]) g0 = g;
    int g1 = -1;
#pragma unroll
    for (int g = 0; g < 4; g++) {
        if (g == g0) continue;
        if (g1 < 0 || gs[g] > gs[g1]) g1 = g;
    }
    int i0 = -1; float v0 = -1.f;
#pragma unroll
    for (int e = 0; e < NE; e++) {
        int g = e >> 1;
        float v = (g == g0 || g == g1) ? sfc[e] : 0.0f;
        if (v > v0) { v0 = v; i0 = e; }
    }
    int i1 = -1; float v1 = -1.f;
#pragma unroll
    for (int e = 0; e < NE; e++) {
        if (e == i0) continue;
        int g = e >> 1;
        float v = (g == g0 || g == g1) ? sfc[e] : 0.0f;
        if (v > v1) { v1 = v; i1 = e; }
    }
    float w0 = scores[i0], w1 = scores[i1];
    float inv = 2.5f / (w0 + w1 + 1e-20f);
    w0 *= inv; w1 *= inv;

    int p0 = atomicAdd(&g_cnt[i0], 1);
    g_rows[i0 * TT + p0] = t;
    g_tok2row[t * 2 + 0] = i0 * TT + p0;
    g_wt[t * 2 + 0]      = w0;
    int p1 = atomicAdd(&g_cnt[i1], 1);
    g_rows[i1 * TT + p1] = t;
    g_tok2row[t * 2 + 1] = i1 * TT + p1;
    g_wt[t * 2 + 1]      = w1;
}

// ---------------- fp16 A-split HMMA GEMM: D = (Ahi+Alo)[M,K] @ B[N,K]^T ----------------
// 128x128 CTA tile, BK=32, 8 warps (4m x 2n), 3-stage cp.async pipeline.
// 2 MMA combo sweeps: Ahi*B, Alo*B. Weights single fp16 plane.
#define ROWB   80
#define PLANEB (128 * ROWB)       // 10240
#define STAGEB (3 * PLANEB)       // 30720 (Ahi, Alo, B)
#define NSTG   3
#define SMEM_SZ (NSTG * STAGEB)   // 92160

template <int N, int K, bool ROUTED, bool GATHER, bool GATEUP>
__global__ __launch_bounds__(256)
void hmma2(const __half* __restrict__ Ahi, const __half* __restrict__ Alo,
           const __half* __restrict__ B,
           float* __restrict__ D,
           __half* __restrict__ Phi, __half* __restrict__ Plo) {
    extern __shared__ __align__(128) char smem[];
    const int e  = blockIdx.z;
    const int M  = ROUTED ? g_cnt[e] : TT;
    const int m0 = blockIdx.y * 128;
    if (m0 >= M) return;
    const int n0   = blockIdx.x * 128;
    const int tid  = threadIdx.x;
    const int lane = tid & 31;
    const int wid  = tid >> 5;
    const int wm   = wid & 3;
    const int wn   = wid >> 2;
    const uint32_t sb0 = smem_u32(smem);

    // loader mapping: 2 threads per row, each thread 2x16B per plane
    const int lr = tid >> 1;
    const int hh = tid & 1;
    const __half *pAhi, *pAlo;
    uint32_t asz = 0;
    {
        int row = m0 + lr;
        size_t gr = 0;
        if (row < M) {
            gr  = GATHER ? (size_t)g_rows[e * TT + row]
                         : (ROUTED ? (size_t)e * TT + row : (size_t)row);
            asz = 16;
        }
        pAhi = Ahi + gr * (size_t)K + hh * 16;
        pAlo = Alo + gr * (size_t)K + hh * 16;
    }
    const __half* pB = B + (ROUTED ? (size_t)e * N * K : 0)
                         + (size_t)(n0 + lr) * K + hh * 16;
    const uint32_t dsto = (uint32_t)lr * ROWB + (uint32_t)hh * 32;

    auto issue = [&](int c, int s) {
        uint32_t d = sb0 + (uint32_t)s * STAGEB + dsto;
        const __half* a0 = pAhi + c * 32;
        const __half* a1 = pAlo + c * 32;
        const __half* b0 = pB   + c * 32;
        cpa16(d,                  a0,     asz);
        cpa16(d + 16,             a0 + 8, asz);
        cpa16(d + PLANEB,         a1,     asz);
        cpa16(d + PLANEB + 16,    a1 + 8, asz);
        cpa16(d + 2 * PLANEB,      b0,     16);
        cpa16(d + 2 * PLANEB + 16, b0 + 8, 16);
        CP_COMMIT();
    };

    float acc[2][8][4];
#pragma unroll
    for (int f = 0; f < 2; f++)
#pragma unroll
        for (int j = 0; j < 8; j++)
#pragma unroll
            for (int q = 0; q < 4; q++) acc[f][j][q] = 0.f;

    const int NCH = K / 32;
    issue(0, 0);
    issue(1, 1);

    for (int c = 0; c < NCH; c++) {
        const int s = c % NSTG;
        if (c + 2 < NCH) {
            issue(c + 2, (c + 2) % NSTG);
            CP_WAIT(2);
        } else if (c + 1 < NCH) {
            CP_WAIT(1);
        } else {
            CP_WAIT(0);
        }
        __syncthreads();

        const uint32_t stg = sb0 + (uint32_t)s * STAGEB;
#pragma unroll
        for (int ks = 0; ks < 2; ks++) {
            const uint32_t cb = (uint32_t)(ks * 16 + (lane >> 4) * 8) * 2;
            uint32_t aH[2][4], aL[2][4], bF[8][2];
#pragma unroll
            for (int f = 0; f < 2; f++) {
                uint32_t ra = (uint32_t)(wm * 32 + f * 16 + (lane & 15)) * ROWB + cb;
                ldsm4(aH[f], stg + ra);
                ldsm4(aL[f], stg + PLANEB + ra);
            }
#pragma unroll
            for (int nb = 0; nb < 4; nb++) {
                uint32_t rb = (uint32_t)(wn * 64 + nb * 16 + (lane & 15)) * ROWB + cb;
                uint32_t h4[4];
                ldsm4(h4, stg + 2 * PLANEB + rb);
                bF[2 * nb][0] = h4[0]; bF[2 * nb][1] = h4[2];
                bF[2 * nb + 1][0] = h4[1]; bF[2 * nb + 1][1] = h4[3];
            }
            // 2 combo sweeps: accumulator reuse distance = 16 MMAs
#pragma unroll
            for (int f = 0; f < 2; f++)
#pragma unroll
                for (int j = 0; j < 8; j++)
                    mma16816(acc[f][j], aH[f], bF[j][0], bF[j][1]);
#pragma unroll
            for (int f = 0; f < 2; f++)
#pragma unroll
                for (int j = 0; j < 8; j++)
                    mma16816(acc[f][j], aL[f], bF[j][0], bF[j][1]);
        }
        __syncthreads();
    }

    // ---- epilogue ----
    const size_t rowbase = ROUTED ? (size_t)e * TT : 0;
#pragma unroll
    for (int f = 0; f < 2; f++) {
#pragma unroll
        for (int half = 0; half < 2; half++) {
            int rloc = m0 + wm * 32 + f * 16 + (lane >> 2) + half * 8;
            if (rloc >= M) continue;
            size_t rg = rowbase + rloc;
#pragma unroll
            for (int j = 0; j < 8; j++) {
                float vx = acc[f][j][half * 2 + 0];
                float vy = acc[f][j][half * 2 + 1];
                int cg = n0 + wn * 64 + j * 8 + (lane & 3) * 2;
                if (GATEUP) {
                    // vx = gate (even col), vy = up (odd col)
                    float a = vx / (1.f + expf(-vx)) * vy;
                    __half h, l;
                    splith(a, h, l);
                    size_t o = rg * (size_t)(N / 2) + (cg >> 1);
                    Phi[o] = h; Plo[o] = l;
                } else {
                    *(float2*)(D + rg * (size_t)N + cg) = make_float2(vx, vy);
                }
            }
        }
    }
}

// ---------------- combine ----------------
__global__ void combine_kernel(float4* __restrict__ out) {
    int idx = blockIdx.x * blockDim.x + threadIdx.x;
    if (idx >= TT * HH / 4) return;
    int t  = idx >> 9;
    int h4 = idx & 511;
    float w0 = g_wt[2 * t], w1 = g_wt[2 * t + 1];
    float4 a = *((const float4*)(g_y + (size_t)g_tok2row[2 * t]     * HH) + h4);
    float4 b = *((const float4*)(g_y + (size_t)g_tok2row[2 * t + 1] * HH) + h4);
    float4 c = *((const float4*)g_ys + idx);
    float4 o;
    o.x = fmaf(w0, a.x, fmaf(w1, b.x, c.x));
    o.y = fmaf(w0, a.y, fmaf(w1, b.y, c.y));
    o.z = fmaf(w0, a.z, fmaf(w1, b.z, c.z));
    o.w = fmaf(w0, a.w, fmaf(w1, b.w, c.w));
    out[idx] = o;
}

// ---------------- launch ----------------
extern "C" void kernel_launch(void* const* d_in, const int* in_sizes, int n_in,
                              void* d_out, int out_size) {
    const float* x    = (const float*)d_in[0];
    const float* rw   = (const float*)d_in[1];
    const float* bias = (const float*)d_in[2];
    const float* gw   = (const float*)d_in[3];
    const float* uw   = (const float*)d_in[4];
    const float* dw   = (const float*)d_in[5];
    const float* sgw  = (const float*)d_in[6];
    const float* suw  = (const float*)d_in[7];
    const float* sdw  = (const float*)d_in[8];
    float* out = (float*)d_out;

    __half *xh, *xl, *w2, *dwp, *sw2, *sdwp, *ah, *al, *ash, *asl;
    float *py, *pys;
    cudaGetSymbolAddress((void**)&xh,   g_xh);   cudaGetSymbolAddress((void**)&xl,   g_xl);
    cudaGetSymbolAddress((void**)&w2,   g_w2);
    cudaGetSymbolAddress((void**)&dwp,  g_dw);
    cudaGetSymbolAddress((void**)&sw2,  g_sw2);
    cudaGetSymbolAddress((void**)&sdwp, g_sdw);
    cudaGetSymbolAddress((void**)&ah,   g_ah);   cudaGetSymbolAddress((void**)&al,   g_al);
    cudaGetSymbolAddress((void**)&ash,  g_ash);  cudaGetSymbolAddress((void**)&asl,  g_asl);
    cudaGetSymbolAddress((void**)&py,   g_y);    cudaGetSymbolAddress((void**)&pys,  g_ys);

    cudaFuncSetAttribute(hmma2<2 * IMOE, HH, true,  true,  true >, cudaFuncAttributeMaxDynamicSharedMemorySize, SMEM_SZ);
    cudaFuncSetAttribute(hmma2<HH, IMOE, true,  false, false>, cudaFuncAttributeMaxDynamicSharedMemorySize, SMEM_SZ);
    cudaFuncSetAttribute(hmma2<2 * ISH,  HH, false, false, true >, cudaFuncAttributeMaxDynamicSharedMemorySize, SMEM_SZ);
    cudaFuncSetAttribute(hmma2<HH,  ISH, false, false, false>, cudaFuncAttributeMaxDynamicSharedMemorySize, SMEM_SZ);

    // launch index:                                                     ncu -s 5 -c 1
    zero_cnt_kernel<<<1, 32>>>();                                     // 0
    router_kernel<<<TT / 8, 256>>>(x, rw, bias);                      // 1

    {   // 2: x -> fp16 hi/lo
        size_t n4 = (size_t)TT * HH / 4;
        cvt_split16<<<(unsigned)((n4 + 255) / 256), 256>>>((const float4*)x,
            (__half2*)xh, (__half2*)xl, n4);
    }
    {   // 3: routed gate/up weights -> interleaved fp16
        size_t total = (size_t)NE * 2 * IMOE * (HH / 4);
        interleave_w16<IMOE, HH><<<(unsigned)((total + 255) / 256), 256>>>(
            (const float4*)gw, (const float4*)uw, (__half2*)w2, NE);
    }
    {   // 4: routed down weights -> fp16
        size_t n4 = (size_t)NE * HH * IMOE / 4;
        cvt_plain16<<<(unsigned)((n4 + 255) / 256), 256>>>((const float4*)dw,
            (__half2*)dwp, n4);
    }

    // 5: MAIN routed gate+up GEMM (profiled by ncu -s 5 -c 1)
    hmma2<2 * IMOE, HH, true, true, true><<<dim3(2 * IMOE / 128, TT / 128, NE), 256, SMEM_SZ>>>(
        xh, xl, w2, nullptr, ah, al);
    // 6: routed down GEMM
    hmma2<HH, IMOE, true, false, false><<<dim3(HH / 128, TT / 128, NE), 256, SMEM_SZ>>>(
        ah, al, dwp, py, nullptr, nullptr);

    {   // 7: shared gate/up weights
        size_t total = (size_t)2 * ISH * (HH / 4);
        interleave_w16<ISH, HH><<<(unsigned)((total + 255) / 256), 256>>>(
            (const float4*)sgw, (const float4*)suw, (__half2*)sw2, 1);
    }
    {   // 8: shared down weights
        size_t n4 = (size_t)HH * ISH / 4;
        cvt_plain16<<<(unsigned)((n4 + 255) / 256), 256>>>((const float4*)sdw,
            (__half2*)sdwp, n4);
    }

    // 9, 10: shared expert GEMMs
    hmma2<2 * ISH, HH, false, false, true><<<dim3(2 * ISH / 128, TT / 128, 1), 256, SMEM_SZ>>>(
        xh, xl, sw2, nullptr, ash, asl);
    hmma2<HH, ISH, false, false, false><<<dim3(HH / 128, TT / 128, 1), 256, SMEM_SZ>>>(
        ash, asl, sdwp, pys, nullptr, nullptr);

    // 11: combine
    combine_kernel<<<(TT * HH / 4 + 255) / 256, 256>>>((float4*)out);
}

// round 9
// speedup vs baseline: 3.2664x; 1.6056x over previous
#include <cuda_runtime.h>
#include <cuda_fp16.h>
#include <math.h>
#include <stdint.h>

#define HH   2048
#define IMOE 1408
#define NE   8
#define TT   2048
#define ISH  2816

// ---------------- scratch (__device__ globals) ----------------
__device__ int   g_cnt[NE];
__device__ int   g_rows[NE * TT];
__device__ int   g_tok2row[TT * 2];
__device__ float g_wt[TT * 2];

__device__ __half g_x16[(size_t)TT * HH];
__device__ __half g_w2 [(size_t)NE * 2 * IMOE * HH];
__device__ __half g_dw [(size_t)NE * HH * IMOE];
__device__ __half g_sw2[(size_t)2 * ISH * HH];
__device__ __half g_sdw[(size_t)HH * ISH];
__device__ __half g_act[(size_t)NE * TT * IMOE];
__device__ __half g_acs[(size_t)TT * ISH];
__device__ float g_y [(size_t)NE * TT * HH];
__device__ float g_ys[(size_t)TT * HH];

// ---------------- helpers ----------------
__device__ __forceinline__ uint32_t smem_u32(const void* p) {
    uint32_t a;
    asm("{ .reg .u64 t; cvta.to.shared.u64 t, %1; cvt.u32.u64 %0, t; }"
        : "=r"(a) : "l"(p));
    return a;
}
__device__ __forceinline__ void ldsm4(uint32_t* r, uint32_t addr) {
    asm volatile("ldmatrix.sync.aligned.m8n8.x4.shared.b16 {%0,%1,%2,%3}, [%4];"
                 : "=r"(r[0]), "=r"(r[1]), "=r"(r[2]), "=r"(r[3]) : "r"(addr));
}
__device__ __forceinline__ void mma16816(float* d, const uint32_t* a,
                                         uint32_t b0, uint32_t b1) {
    asm volatile("mma.sync.aligned.m16n8k16.row.col.f32.f16.f16.f32 "
                 "{%0,%1,%2,%3}, {%4,%5,%6,%7}, {%8,%9}, {%0,%1,%2,%3};"
                 : "+f"(d[0]), "+f"(d[1]), "+f"(d[2]), "+f"(d[3])
                 : "r"(a[0]), "r"(a[1]), "r"(a[2]), "r"(a[3]), "r"(b0), "r"(b1));
}
__device__ __forceinline__ void cpa16(uint32_t dst, const void* src, uint32_t sz) {
    asm volatile("cp.async.cg.shared.global [%0], [%1], 16, %2;"
                 :: "r"(dst), "l"(src), "r"(sz) : "memory");
}
#define CP_COMMIT() asm volatile("cp.async.commit_group;" ::: "memory")
#define CP_WAIT(n)  asm volatile("cp.async.wait_group %0;" :: "n"(n) : "memory")

// ---------------- conversion kernels ----------------
__global__ void cvt_plain16(const float4* __restrict__ src,
                            __half2* __restrict__ dst, size_t n4) {
    size_t stride = (size_t)gridDim.x * blockDim.x;
    for (size_t i = (size_t)blockIdx.x * blockDim.x + threadIdx.x; i < n4; i += stride) {
        float4 v = src[i];
        dst[2 * i]     = __half2(__float2half_rn(v.x), __float2half_rn(v.y));
        dst[2 * i + 1] = __half2(__float2half_rn(v.z), __float2half_rn(v.w));
    }
}

// interleave gate/up rows to single fp16 plane: dst row n -> (n&1 ? up : gate)[n>>1]
template <int NI, int K>
__global__ void interleave_w16(const float4* __restrict__ gsrc,
                               const float4* __restrict__ usrc,
                               __half2* __restrict__ dst, int E) {
    const int K4 = K / 4;
    size_t total = (size_t)E * 2 * NI * K4;
    size_t stride = (size_t)gridDim.x * blockDim.x;
    for (size_t i = (size_t)blockIdx.x * blockDim.x + threadIdx.x; i < total; i += stride) {
        int    k4  = (int)(i % K4);
        size_t row = i / K4;
        int    n   = (int)(row % (2 * NI));
        int    e   = (int)(row / (2 * NI));
        const float4* s = (n & 1) ? usrc : gsrc;
        float4 v = s[((size_t)e * NI + (n >> 1)) * K4 + k4];
        dst[2 * i]     = __half2(__float2half_rn(v.x), __float2half_rn(v.y));
        dst[2 * i + 1] = __half2(__float2half_rn(v.z), __float2half_rn(v.w));
    }
}

// ---------------- misc kernels ----------------
__global__ void zero_cnt_kernel() {
    if (threadIdx.x < NE) g_cnt[threadIdx.x] = 0;
}

__global__ void router_kernel(const float* __restrict__ x,
                              const float* __restrict__ rw,
                              const float* __restrict__ bias) {
    int t    = (blockIdx.x * blockDim.x + threadIdx.x) >> 5;
    int lane = threadIdx.x & 31;
    if (t >= TT) return;
    const float* xt = x + (size_t)t * HH;

    float logits[NE];
#pragma unroll
    for (int e = 0; e < NE; e++) {
        const float* w = rw + e * HH;
        float s = 0.f;
        for (int h = lane; h < HH; h += 32) s = fmaf(xt[h], w[h], s);
#pragma unroll
        for (int o = 16; o; o >>= 1) s += __shfl_xor_sync(0xffffffffu, s, o);
        logits[e] = s;
    }
    if (lane != 0) return;

    float scores[NE], sfc[NE];
#pragma unroll
    for (int e = 0; e < NE; e++) {
        scores[e] = 1.f / (1.f + expf(-logits[e]));
        sfc[e]    = scores[e] + bias[e];
    }
    float gs[4];
#pragma unroll
    for (int g = 0; g < 4; g++) gs[g] = sfc[2 * g] + sfc[2 * g + 1];
    int g0 = 0;
#pragma unroll
    for (int g = 1; g < 4; g++) if (gs[g] > gs[g0]) g0 = g;
    int g1 = -1;
#pragma unroll
    for (int g = 0; g < 4; g++) {
        if (g == g0) continue;
        if (g1 < 0 || gs[g] > gs[g1]) g1 = g;
    }
    int i0 = -1; float v0 = -1.f;
#pragma unroll
    for (int e = 0; e < NE; e++) {
        int g = e >> 1;
        float v = (g == g0 || g == g1) ? sfc[e] : 0.0f;
        if (v > v0) { v0 = v; i0 = e; }
    }
    int i1 = -1; float v1 = -1.f;
#pragma unroll
    for (int e = 0; e < NE; e++) {
        if (e == i0) continue;
        int g = e >> 1;
        float v = (g == g0 || g == g1) ? sfc[e] : 0.0f;
        if (v > v1) { v1 = v; i1 = e; }
    }
    float w0 = scores[i0], w1 = scores[i1];
    float inv = 2.5f / (w0 + w1 + 1e-20f);
    w0 *= inv; w1 *= inv;

    int p0 = atomicAdd(&g_cnt[i0], 1);
    g_rows[i0 * TT + p0] = t;
    g_tok2row[t * 2 + 0] = i0 * TT + p0;
    g_wt[t * 2 + 0]      = w0;
    int p1 = atomicAdd(&g_cnt[i1], 1);
    g_rows[i1 * TT + p1] = t;
    g_tok2row[t * 2 + 1] = i1 * TT + p1;
    g_wt[t * 2 + 1]      = w1;
}

// ---------------- fp16 HMMA GEMM: D[M,N] = A[M,K] @ B[N,K]^T ----------------
// 128x128 CTA tile, BK=32, 8 warps (4m x 2n), 3-stage cp.async pipeline.
#define ROWB   80
#define PLANEB (128 * ROWB)       // 10240
#define STAGEB (2 * PLANEB)       // 20480 (A, B)
#define NSTG   3
#define SMEM_SZ (NSTG * STAGEB)   // 61440

template <int N, int K, bool ROUTED, bool GATHER, bool GATEUP>
__global__ __launch_bounds__(256)
void hmma1(const __half* __restrict__ A, const __half* __restrict__ B,
           float* __restrict__ D, __half* __restrict__ P) {
    extern __shared__ __align__(128) char smem[];
    const int e  = blockIdx.z;
    const int M  = ROUTED ? g_cnt[e] : TT;
    const int m0 = blockIdx.y * 128;
    if (m0 >= M) return;
    const int n0   = blockIdx.x * 128;
    const int tid  = threadIdx.x;
    const int lane = tid & 31;
    const int wid  = tid >> 5;
    const int wm   = wid & 3;
    const int wn   = wid >> 2;
    const uint32_t sb0 = smem_u32(smem);

    // loader mapping: 2 threads per row, each thread 2x16B per plane
    const int lr = tid >> 1;
    const int hh = tid & 1;
    const __half* pA;
    uint32_t asz = 0;
    {
        int row = m0 + lr;
        size_t gr = 0;
        if (row < M) {
            gr  = GATHER ? (size_t)g_rows[e * TT + row]
                         : (ROUTED ? (size_t)e * TT + row : (size_t)row);
            asz = 16;
        }
        pA = A + gr * (size_t)K + hh * 16;
    }
    const __half* pB = B + (ROUTED ? (size_t)e * N * K : 0)
                         + (size_t)(n0 + lr) * K + hh * 16;
    const uint32_t dsto = (uint32_t)lr * ROWB + (uint32_t)hh * 32;

    auto issue = [&](int c, int s) {
        uint32_t d = sb0 + (uint32_t)s * STAGEB + dsto;
        const __half* a0 = pA + c * 32;
        const __half* b0 = pB + c * 32;
        cpa16(d,               a0,     asz);
        cpa16(d + 16,          a0 + 8, asz);
        cpa16(d + PLANEB,      b0,     16);
        cpa16(d + PLANEB + 16, b0 + 8, 16);
        CP_COMMIT();
    };

    float acc[2][8][4];
#pragma unroll
    for (int f = 0; f < 2; f++)
#pragma unroll
        for (int j = 0; j < 8; j++)
#pragma unroll
            for (int q = 0; q < 4; q++) acc[f][j][q] = 0.f;

    const int NCH = K / 32;
    issue(0, 0);
    issue(1, 1);

    for (int c = 0; c < NCH; c++) {
        const int s = c % NSTG;
        if (c + 2 < NCH) {
            issue(c + 2, (c + 2) % NSTG);
            CP_WAIT(2);
        } else if (c + 1 < NCH) {
            CP_WAIT(1);
        } else {
            CP_WAIT(0);
        }
        __syncthreads();

        const uint32_t stg = sb0 + (uint32_t)s * STAGEB;
#pragma unroll
        for (int ks = 0; ks < 2; ks++) {
            const uint32_t cb = (uint32_t)(ks * 16 + (lane >> 4) * 8) * 2;
            uint32_t aF[2][4], bF[8][2];
#pragma unroll
            for (int f = 0; f < 2; f++) {
                uint32_t ra = (uint32_t)(wm * 32 + f * 16 + (lane & 15)) * ROWB + cb;
                ldsm4(aF[f], stg + ra);
            }
#pragma unroll
            for (int nb = 0; nb < 4; nb++) {
                uint32_t rb = (uint32_t)(wn * 64 + nb * 16 + (lane & 15)) * ROWB + cb;
                uint32_t h4[4];
                ldsm4(h4, stg + PLANEB + rb);
                bF[2 * nb][0] = h4[0]; bF[2 * nb][1] = h4[2];
                bF[2 * nb + 1][0] = h4[1]; bF[2 * nb + 1][1] = h4[3];
            }
#pragma unroll
            for (int f = 0; f < 2; f++)
#pragma unroll
                for (int j = 0; j < 8; j++)
                    mma16816(acc[f][j], aF[f], bF[j][0], bF[j][1]);
        }
        __syncthreads();
    }

    // ---- epilogue ----
    const size_t rowbase = ROUTED ? (size_t)e * TT : 0;
#pragma unroll
    for (int f = 0; f < 2; f++) {
#pragma unroll
        for (int half = 0; half < 2; half++) {
            int rloc = m0 + wm * 32 + f * 16 + (lane >> 2) + half * 8;
            if (rloc >= M) continue;
            size_t rg = rowbase + rloc;
#pragma unroll
            for (int j = 0; j < 8; j++) {
                float vx = acc[f][j][half * 2 + 0];
                float vy = acc[f][j][half * 2 + 1];
                int cg = n0 + wn * 64 + j * 8 + (lane & 3) * 2;
                if (GATEUP) {
                    // vx = gate (even col), vy = up (odd col)
                    float a = vx / (1.f + expf(-vx)) * vy;
                    P[rg * (size_t)(N / 2) + (cg >> 1)] = __float2half_rn(a);
                } else {
                    *(float2*)(D + rg * (size_t)N + cg) = make_float2(vx, vy);
                }
            }
        }
    }
}

// ---------------- combine ----------------
__global__ void combine_kernel(float4* __restrict__ out) {
    int idx = blockIdx.x * blockDim.x + threadIdx.x;
    if (idx >= TT * HH / 4) return;
    int t  = idx >> 9;
    int h4 = idx & 511;
    float w0 = g_wt[2 * t], w1 = g_wt[2 * t + 1];
    float4 a = *((const float4*)(g_y + (size_t)g_tok2row[2 * t]     * HH) + h4);
    float4 b = *((const float4*)(g_y + (size_t)g_tok2row[2 * t + 1] * HH) + h4);
    float4 c = *((const float4*)g_ys + idx);
    float4 o;
    o.x = fmaf(w0, a.x, fmaf(w1, b.x, c.x));
    o.y = fmaf(w0, a.y, fmaf(w1, b.y, c.y));
    o.z = fmaf(w0, a.z, fmaf(w1, b.z, c.z));
    o.w = fmaf(w0, a.w, fmaf(w1, b.w, c.w));
    out[idx] = o;
}

// ---------------- launch ----------------
extern "C" void kernel_launch(void* const* d_in, const int* in_sizes, int n_in,
                              void* d_out, int out_size) {
    const float* x    = (const float*)d_in[0];
    const float* rw   = (const float*)d_in[1];
    const float* bias = (const float*)d_in[2];
    const float* gw   = (const float*)d_in[3];
    const float* uw   = (const float*)d_in[4];
    const float* dw   = (const float*)d_in[5];
    const float* sgw  = (const float*)d_in[6];
    const float* suw  = (const float*)d_in[7];
    const float* sdw  = (const float*)d_in[8];
    float* out = (float*)d_out;

    __half *x16, *w2, *dwp, *sw2, *sdwp, *act, *acs;
    float *py, *pys;
    cudaGetSymbolAddress((void**)&x16,  g_x16);
    cudaGetSymbolAddress((void**)&w2,   g_w2);
    cudaGetSymbolAddress((void**)&dwp,  g_dw);
    cudaGetSymbolAddress((void**)&sw2,  g_sw2);
    cudaGetSymbolAddress((void**)&sdwp, g_sdw);
    cudaGetSymbolAddress((void**)&act,  g_act);
    cudaGetSymbolAddress((void**)&acs,  g_acs);
    cudaGetSymbolAddress((void**)&py,   g_y);
    cudaGetSymbolAddress((void**)&pys,  g_ys);

    cudaFuncSetAttribute(hmma1<2 * IMOE, HH, true,  true,  true >, cudaFuncAttributeMaxDynamicSharedMemorySize, SMEM_SZ);
    cudaFuncSetAttribute(hmma1<HH, IMOE, true,  false, false>, cudaFuncAttributeMaxDynamicSharedMemorySize, SMEM_SZ);
    cudaFuncSetAttribute(hmma1<2 * ISH,  HH, false, false, true >, cudaFuncAttributeMaxDynamicSharedMemorySize, SMEM_SZ);
    cudaFuncSetAttribute(hmma1<HH,  ISH, false, false, false>, cudaFuncAttributeMaxDynamicSharedMemorySize, SMEM_SZ);

    // launch index:                                                     ncu -s 5 -c 1
    zero_cnt_kernel<<<1, 32>>>();                                     // 0
    router_kernel<<<TT / 8, 256>>>(x, rw, bias);                      // 1

    {   // 2: x -> fp16
        size_t n4 = (size_t)TT * HH / 4;
        cvt_plain16<<<(unsigned)((n4 + 255) / 256), 256>>>((const float4*)x,
            (__half2*)x16, n4);
    }
    {   // 3: routed gate/up weights -> interleaved fp16
        size_t total = (size_t)NE * 2 * IMOE * (HH / 4);
        interleave_w16<IMOE, HH><<<(unsigned)((total + 255) / 256), 256>>>(
            (const float4*)gw, (const float4*)uw, (__half2*)w2, NE);
    }
    {   // 4: routed down weights -> fp16
        size_t n4 = (size_t)NE * HH * IMOE / 4;
        cvt_plain16<<<(unsigned)((n4 + 255) / 256), 256>>>((const float4*)dw,
            (__half2*)dwp, n4);
    }

    // 5: MAIN routed gate+up GEMM (profiled by ncu -s 5 -c 1)
    hmma1<2 * IMOE, HH, true, true, true><<<dim3(2 * IMOE / 128, TT / 128, NE), 256, SMEM_SZ>>>(
        x16, w2, nullptr, act);
    // 6: routed down GEMM
    hmma1<HH, IMOE, true, false, false><<<dim3(HH / 128, TT / 128, NE), 256, SMEM_SZ>>>(
        act, dwp, py, nullptr);

    {   // 7: shared gate/up weights
        size_t total = (size_t)2 * ISH * (HH / 4);
        interleave_w16<ISH, HH><<<(unsigned)((total + 255) / 256), 256>>>(
            (const float4*)sgw, (const float4*)suw, (__half2*)sw2, 1);
    }
    {   // 8: shared down weights
        size_t n4 = (size_t)HH * ISH / 4;
        cvt_plain16<<<(unsigned)((n4 + 255) / 256), 256>>>((const float4*)sdw,
            (__half2*)sdwp, n4);
    }

    // 9, 10: shared expert GEMMs
    hmma1<2 * ISH, HH, false, false, true><<<dim3(2 * ISH / 128, TT / 128, 1), 256, SMEM_SZ>>>(
        x16, sw2, nullptr, acs);
    hmma1<HH, ISH, false, false, false><<<dim3(HH / 128, TT / 128, 1), 256, SMEM_SZ>>>(
        acs, sdwp, pys, nullptr);

    // 11: combine
    combine_kernel<<<(TT * HH / 4 + 255) / 256, 256>>>((float4*)out);
}